// round 13
// baseline (speedup 1.0000x reference)
#include <cuda_runtime.h>
#include <cstdint>

// out[b,j] = input2[b,j] * sum_i input1[b,i] * w2[i,j],  w2 = weights.sum(axis=2)
// B=16384, I=64, J=2048, K=64. fp32 in/out; GEMM in tf32 mma.sync.

#define B_DIM 16384
#define I_DIM 64
#define J_DIM 2048
#define K_DIM 64

__device__ float g_w2[I_DIM * J_DIM];   // K-reduced weights (tf32-rounded fp32 bits)

__device__ __forceinline__ uint32_t f32_to_tf32(float f) {
    uint32_t t;
    asm("cvt.rna.tf32.f32 %0, %1;" : "=r"(t) : "f"(f));
    return t;
}

// ---------------------------------------------------------------------------
// Kernel 1: w2[i,j] = sum_k weights[i,j,k]. 4 threads/row, 4x LDG.128 each.
// ---------------------------------------------------------------------------
__global__ void reduce_w_kernel(const float* __restrict__ w) {
    int gtid = blockIdx.x * blockDim.x + threadIdx.x;
    int row  = gtid >> 2;          // (i*J + j)
    int q    = gtid & 3;
    const float* p = w + (size_t)row * K_DIM + q * 16;
    float4 v0 = *(const float4*)(p + 0);
    float4 v1 = *(const float4*)(p + 4);
    float4 v2 = *(const float4*)(p + 8);
    float4 v3 = *(const float4*)(p + 12);
    float s = ((v0.x + v0.y) + (v0.z + v0.w)) + ((v1.x + v1.y) + (v1.z + v1.w))
            + ((v2.x + v2.y) + (v2.z + v2.w)) + ((v3.x + v3.y) + (v3.z + v3.w));
    s += __shfl_xor_sync(0xffffffffu, s, 1);
    s += __shfl_xor_sync(0xffffffffu, s, 2);
    if (q == 0) g_w2[row] = __uint_as_float(f32_to_tf32(s));
}

// ---------------------------------------------------------------------------
// Kernel 2: tf32 tensor-core GEMM (x1 @ w2) * x2.
// Block tile 128(B) x 64(J), 8 warps, warp tile 32x32 (2 m16 x 4 n8 frags).
// 3 CTAs/SM target (<=85 regs). Grid: b-tiles fastest (L2 w2 reuse).
// ---------------------------------------------------------------------------
#define SA 68    // x1s row stride (floats)
#define SB 72    // w2s row stride (floats): bank = (8k + col) % 32 distinct

__device__ __forceinline__ void mma_tf32(float* d, const uint32_t* a,
                                         uint32_t b0, uint32_t b1) {
    asm volatile(
        "mma.sync.aligned.m16n8k8.row.col.f32.tf32.tf32.f32 "
        "{%0,%1,%2,%3}, {%4,%5,%6,%7}, {%8,%9}, {%0,%1,%2,%3};"
        : "+f"(d[0]), "+f"(d[1]), "+f"(d[2]), "+f"(d[3])
        : "r"(a[0]), "r"(a[1]), "r"(a[2]), "r"(a[3]), "r"(b0), "r"(b1));
}

__global__ void __launch_bounds__(256, 3)
gemm_mul_kernel(const float* __restrict__ x1,
                const float* __restrict__ x2,
                float* __restrict__ out) {
    extern __shared__ float smem[];
    float* x1s = smem;                 // [128][SA]
    float* w2s = smem + 128 * SA;      // [64][SB]

    const int tid    = threadIdx.x;
    const int wid    = tid >> 5;
    const int lane   = tid & 31;
    const int g      = lane >> 2;      // 0..7
    const int tq     = lane & 3;       // 0..3
    const int warp_m = wid & 3;        // 4 warps x 32 rows
    const int warp_n = wid >> 2;       // 2 warps x 32 cols
    const int j0     = blockIdx.y * 64;
    const int b0     = blockIdx.x * 128;

    // ---- Fill x1s [128 x 64], tf32-convert. u fast across lanes:
    // coalesced LDG (16 lanes span one 256B row); STS conflict-free
    // (16 consecutive 16B units per row at 17r+u).
    #pragma unroll
    for (int k = 0; k < 8; k++) {
        int idx = tid + k * 256;             // 128 rows x 16 float4
        int u   = idx & 15;
        int r   = idx >> 4;
        float4 v = *(const float4*)(&x1[(size_t)(b0 + r) * I_DIM + u * 4]);
        float4 o;
        o.x = __uint_as_float(f32_to_tf32(v.x));
        o.y = __uint_as_float(f32_to_tf32(v.y));
        o.z = __uint_as_float(f32_to_tf32(v.z));
        o.w = __uint_as_float(f32_to_tf32(v.w));
        *(float4*)(&x1s[r * SA + u * 4]) = o;
    }
    // ---- Fill w2s [64 x 64] (already tf32) ----
    #pragma unroll
    for (int k = 0; k < 4; k++) {
        int idx = tid + k * 256;             // 64 rows x 16 float4
        int i   = idx >> 4;
        int c4  = idx & 15;
        float4 v = *(const float4*)(&g_w2[(size_t)i * J_DIM + j0 + c4 * 4]);
        *(float4*)(&w2s[i * SB + c4 * 4]) = v;
    }
    __syncthreads();

    float acc[2][4][4];
    #pragma unroll
    for (int m = 0; m < 2; m++)
        #pragma unroll
        for (int n = 0; n < 4; n++)
            #pragma unroll
            for (int q = 0; q < 4; q++) acc[m][n][q] = 0.0f;

    const int arow = warp_m * 32;
    const int bcol = warp_n * 32;

    #pragma unroll
    for (int k0 = 0; k0 < K_DIM; k0 += 8) {
        uint32_t A[2][4];
        #pragma unroll
        for (int m = 0; m < 2; m++) {
            int r0 = arow + m * 16 + g;
            int r1 = r0 + 8;
            A[m][0] = __float_as_uint(x1s[r0 * SA + k0 + tq]);
            A[m][1] = __float_as_uint(x1s[r1 * SA + k0 + tq]);
            A[m][2] = __float_as_uint(x1s[r0 * SA + k0 + tq + 4]);
            A[m][3] = __float_as_uint(x1s[r1 * SA + k0 + tq + 4]);
        }
        #pragma unroll
        for (int n = 0; n < 4; n++) {
            int col = bcol + n * 8 + g;
            uint32_t B0 = __float_as_uint(w2s[(k0 + tq) * SB + col]);
            uint32_t B1 = __float_as_uint(w2s[(k0 + tq + 4) * SB + col]);
            mma_tf32(acc[0][n], A[0], B0, B1);
            mma_tf32(acc[1][n], A[1], B0, B1);
        }
    }

    // ---- Epilogue: batch ALL 16 x2 loads first (MLP=16), then mul+store ----
    size_t base[2][2];
    #pragma unroll
    for (int m = 0; m < 2; m++) {
        int r0 = b0 + arow + m * 16 + g;
        base[m][0] = (size_t)r0 * J_DIM + j0 + bcol + tq * 2;
        base[m][1] = base[m][0] + (size_t)8 * J_DIM;
    }
    float2 xv[2][2][4];
    #pragma unroll
    for (int m = 0; m < 2; m++)
        #pragma unroll
        for (int h = 0; h < 2; h++)
            #pragma unroll
            for (int n = 0; n < 4; n++)
                xv[m][h][n] = *(const float2*)(&x2[base[m][h] + n * 8]);
    #pragma unroll
    for (int m = 0; m < 2; m++)
        #pragma unroll
        for (int n = 0; n < 4; n++) {
            float2 ra, rb;
            ra.x = acc[m][n][0] * xv[m][0][n].x;
            ra.y = acc[m][n][1] * xv[m][0][n].y;
            rb.x = acc[m][n][2] * xv[m][1][n].x;
            rb.y = acc[m][n][3] * xv[m][1][n].y;
            *(float2*)(&out[base[m][0] + n * 8]) = ra;
            *(float2*)(&out[base[m][1] + n * 8]) = rb;
        }
}

// ---------------------------------------------------------------------------
extern "C" void kernel_launch(void* const* d_in, const int* in_sizes, int n_in,
                              void* d_out, int out_size) {
    const float* x1 = (const float*)d_in[0];  // (B, I)
    const float* x2 = (const float*)d_in[1];  // (B, J)
    const float* w  = (const float*)d_in[2];  // (I, J, K)
    float* out      = (float*)d_out;          // (B, J)

    // Kernel 1: 131072 rows x 4 threads = 524288 threads.
    reduce_w_kernel<<<(I_DIM * J_DIM * 4) / 256, 256>>>(w);

    // Kernel 2: GEMM + multiply. b-tiles fastest in the grid.
    const int smem_bytes = (128 * SA + 64 * SB) * 4;   // 53248 B
    cudaFuncSetAttribute(gemm_mul_kernel,
                         cudaFuncAttributeMaxDynamicSharedMemorySize, smem_bytes);
    dim3 grid(B_DIM / 128, J_DIM / 64);                // (128, 32)
    gemm_mul_kernel<<<grid, 256, smem_bytes>>>(x1, x2, out);
}